// round 1
// baseline (speedup 1.0000x reference)
#include <cuda_runtime.h>
#include <math.h>

#define Bb 2
#define Tt 2048
#define Cc 1024
#define Hh 16
#define Dd 64
#define BT (Bb*Tt)
#define RMS_EPS 1.1920928955078125e-07f

// Scratch (allocation-free: device globals)
__device__ float g_Q[(size_t)Bb*Hh*Tt*Dd];
__device__ float g_K[(size_t)Bb*Hh*Tt*Dd];
__device__ float g_V[(size_t)Bb*Hh*Tt*Dd];
__device__ float g_O[(size_t)Bb*Hh*Tt*Dd];

// ---------------------------------------------------------------------------
// Kernel 1: QKV projection GEMM (128x64 tile) + RMSNorm + RoPE epilogue.
// blockIdx.y = mat*16 + head  (mat: 0=q,1=k,2=v). One 64-col tile == one head.
// ---------------------------------------------------------------------------
__global__ __launch_bounds__(256) void qkv_kernel(
    const float* __restrict__ x,
    const float* __restrict__ wq,
    const float* __restrict__ wk,
    const float* __restrict__ wv)
{
    __shared__ float As[16][128];
    __shared__ float Bs[16][64];
    __shared__ float Cs[128][68];
    __shared__ float invf[32];
    __shared__ float rowscale[128];

    const int tid = threadIdx.x;
    const int mat = blockIdx.y >> 4;
    const int head = blockIdx.y & 15;
    const int rowBase = blockIdx.x * 128;
    const int cBase = head * 64;
    const float* W = (mat == 0) ? wq : ((mat == 1) ? wk : wv);

    if (tid < 32)
        invf[tid] = 1.0f / powf(10000.0f, (float)(2 * tid) * (1.0f / 64.0f));

    const int tx = tid & 15, ty = tid >> 4;
    float acc[8][4];
    #pragma unroll
    for (int i = 0; i < 8; i++)
        #pragma unroll
        for (int j = 0; j < 4; j++) acc[i][j] = 0.f;

    for (int k0 = 0; k0 < Cc; k0 += 16) {
        #pragma unroll
        for (int l = 0; l < 2; l++) {
            int fid = tid + l * 256;
            int m = fid >> 2;
            int kq = (fid & 3) << 2;
            float4 v = *(const float4*)(x + (size_t)(rowBase + m) * Cc + k0 + kq);
            As[kq + 0][m] = v.x; As[kq + 1][m] = v.y;
            As[kq + 2][m] = v.z; As[kq + 3][m] = v.w;
        }
        {
            int c = tid >> 2;
            int kq = (tid & 3) << 2;
            float4 v = *(const float4*)(W + (size_t)(cBase + c) * Cc + k0 + kq);
            Bs[kq + 0][c] = v.x; Bs[kq + 1][c] = v.y;
            Bs[kq + 2][c] = v.z; Bs[kq + 3][c] = v.w;
        }
        __syncthreads();
        #pragma unroll
        for (int kk = 0; kk < 16; kk++) {
            float4 a0 = *(const float4*)&As[kk][ty * 8];
            float4 a1 = *(const float4*)&As[kk][ty * 8 + 4];
            float4 b0 = *(const float4*)&Bs[kk][tx * 4];
            float a[8] = {a0.x, a0.y, a0.z, a0.w, a1.x, a1.y, a1.z, a1.w};
            float bb[4] = {b0.x, b0.y, b0.z, b0.w};
            #pragma unroll
            for (int i = 0; i < 8; i++)
                #pragma unroll
                for (int j = 0; j < 4; j++)
                    acc[i][j] = fmaf(a[i], bb[j], acc[i][j]);
        }
        __syncthreads();
    }

    #pragma unroll
    for (int i = 0; i < 8; i++) {
        float4 v = make_float4(acc[i][0], acc[i][1], acc[i][2], acc[i][3]);
        *(float4*)&Cs[ty * 8 + i][tx * 4] = v;
    }
    __syncthreads();

    const int r2 = tid >> 1, half = tid & 1;
    // RMSNorm sum of squares (2 threads / row)
    float ss = 0.f;
    #pragma unroll
    for (int c = 0; c < 32; c++) {
        float v = Cs[r2][half * 32 + c];
        ss += v * v;
    }
    ss += __shfl_xor_sync(0xffffffffu, ss, 1);
    if (half == 0)
        rowscale[r2] = rsqrtf(ss * (1.0f / 64.0f) + RMS_EPS);
    __syncthreads();

    const int rGlob = rowBase + r2;
    const int b = rGlob >> 11;
    const int t = rGlob & (Tt - 1);
    float* dst = ((mat == 0) ? g_Q : (mat == 1) ? g_K : g_V)
                 + ((size_t)(b * Hh + head) * Tt + t) * Dd;

    if (mat == 2) {
        #pragma unroll 8
        for (int i = 0; i < 32; i++)
            dst[half * 32 + i] = Cs[r2][half * 32 + i];
    } else {
        float scl = rowscale[r2];
        float tf = (float)t;
        #pragma unroll 4
        for (int i = 0; i < 32; i++) {
            float x1 = Cs[r2][i] * scl;
            float x2 = Cs[r2][i + 32] * scl;
            float sn, cn;
            sincosf(tf * invf[i], &sn, &cn);
            dst[half * 32 + i] = (half == 0) ? fmaf(x1, cn, x2 * sn)
                                             : fmaf(x2, cn, -x1 * sn);
        }
    }
}

// ---------------------------------------------------------------------------
// Kernel 2: fp32 flash attention, 64x64 tiles, causal (lower-tri tiles only).
// P tile aliases the K SMEM buffer. Dynamic SMEM = 3 * 64*68 * 4 = 52224 B.
// ---------------------------------------------------------------------------
__global__ __launch_bounds__(256) void attn_kernel()
{
    extern __shared__ __align__(16) float sm[];
    float* Qs  = sm;                 // [64][68]
    float* KPs = sm + 64 * 68;       // K tile, then re-used for P
    float* Vs  = sm + 2 * 64 * 68;

    const int tid = threadIdx.x;
    const int qTile = (int)(gridDim.x - 1) - (int)blockIdx.x;  // heavy first
    const int bh = blockIdx.y;
    const int qBase = qTile * 64;
    const float* gq = g_Q + (size_t)bh * Tt * Dd;
    const float* gk = g_K + (size_t)bh * Tt * Dd;
    const float* gv = g_V + (size_t)bh * Tt * Dd;
    float* go = g_O + (size_t)bh * Tt * Dd;

    const int tx = tid & 15, ty = tid >> 4;

    #pragma unroll
    for (int l = 0; l < 4; l++) {
        int fid = tid + l * 256;
        int s = fid >> 4, dq = (fid & 15) << 2;
        *(float4*)&Qs[s * 68 + dq] =
            *(const float4*)(gq + (size_t)(qBase + s) * Dd + dq);
    }

    float m_run[4], l_run[4], o[4][4];
    #pragma unroll
    for (int i = 0; i < 4; i++) {
        m_run[i] = -INFINITY; l_run[i] = 0.f;
        #pragma unroll
        for (int j = 0; j < 4; j++) o[i][j] = 0.f;
    }

    for (int kt = 0; kt <= qTile; kt++) {
        const int kBase = kt * 64;
        __syncthreads();   // previous PV done with KPs/Vs
        #pragma unroll
        for (int l = 0; l < 4; l++) {
            int fid = tid + l * 256;
            int s = fid >> 4, dq = (fid & 15) << 2;
            *(float4*)&KPs[s * 68 + dq] =
                *(const float4*)(gk + (size_t)(kBase + s) * Dd + dq);
            *(float4*)&Vs[s * 68 + dq] =
                *(const float4*)(gv + (size_t)(kBase + s) * Dd + dq);
        }
        __syncthreads();

        // S = Q K^T (4x4 per thread)
        float acc[4][4];
        #pragma unroll
        for (int i = 0; i < 4; i++)
            #pragma unroll
            for (int j = 0; j < 4; j++) acc[i][j] = 0.f;

        #pragma unroll
        for (int d0 = 0; d0 < 64; d0 += 4) {
            float av[4][4], bv[4][4];
            #pragma unroll
            for (int i = 0; i < 4; i++) {
                float4 t4 = *(const float4*)&Qs[(ty * 4 + i) * 68 + d0];
                av[i][0] = t4.x; av[i][1] = t4.y; av[i][2] = t4.z; av[i][3] = t4.w;
            }
            #pragma unroll
            for (int j = 0; j < 4; j++) {
                float4 t4 = *(const float4*)&KPs[(tx * 4 + j) * 68 + d0];
                bv[j][0] = t4.x; bv[j][1] = t4.y; bv[j][2] = t4.z; bv[j][3] = t4.w;
            }
            #pragma unroll
            for (int i = 0; i < 4; i++)
                #pragma unroll
                for (int j = 0; j < 4; j++)
                    #pragma unroll
                    for (int u = 0; u < 4; u++)
                        acc[i][j] = fmaf(av[i][u], bv[j][u], acc[i][j]);
        }

        const float SC = 0.125f;  // 1/sqrt(64)
        if (kt == qTile) {
            #pragma unroll
            for (int i = 0; i < 4; i++)
                #pragma unroll
                for (int j = 0; j < 4; j++) {
                    int qp = qBase + ty * 4 + i;
                    int kp = kBase + tx * 4 + j;
                    acc[i][j] = (kp <= qp) ? acc[i][j] * SC : -INFINITY;
                }
        } else {
            #pragma unroll
            for (int i = 0; i < 4; i++)
                #pragma unroll
                for (int j = 0; j < 4; j++) acc[i][j] *= SC;
        }

        // online softmax (row reductions across the 16 lanes sharing ty)
        float p[4][4];
        #pragma unroll
        for (int i = 0; i < 4; i++) {
            float mx = fmaxf(fmaxf(acc[i][0], acc[i][1]),
                             fmaxf(acc[i][2], acc[i][3]));
            #pragma unroll
            for (int off = 8; off; off >>= 1)
                mx = fmaxf(mx, __shfl_xor_sync(0xffffffffu, mx, off, 16));
            float m_new = fmaxf(m_run[i], mx);
            float corr = __expf(m_run[i] - m_new);
            float rs = 0.f;
            #pragma unroll
            for (int j = 0; j < 4; j++) {
                p[i][j] = __expf(acc[i][j] - m_new);
                rs += p[i][j];
            }
            #pragma unroll
            for (int off = 8; off; off >>= 1)
                rs += __shfl_xor_sync(0xffffffffu, rs, off, 16);
            l_run[i] = l_run[i] * corr + rs;
            m_run[i] = m_new;
            #pragma unroll
            for (int j = 0; j < 4; j++) o[i][j] *= corr;
        }

        __syncthreads();   // all done reading KPs as K
        #pragma unroll
        for (int i = 0; i < 4; i++)
            *(float4*)&KPs[(ty * 4 + i) * 68 + tx * 4] =
                make_float4(p[i][0], p[i][1], p[i][2], p[i][3]);
        __syncthreads();

        // O += P V
        #pragma unroll
        for (int s0 = 0; s0 < 64; s0 += 4) {
            float pr[4][4], vm[4][4];
            #pragma unroll
            for (int i = 0; i < 4; i++) {
                float4 t4 = *(const float4*)&KPs[(ty * 4 + i) * 68 + s0];
                pr[i][0] = t4.x; pr[i][1] = t4.y; pr[i][2] = t4.z; pr[i][3] = t4.w;
            }
            #pragma unroll
            for (int u = 0; u < 4; u++) {
                float4 t4 = *(const float4*)&Vs[(s0 + u) * 68 + tx * 4];
                vm[u][0] = t4.x; vm[u][1] = t4.y; vm[u][2] = t4.z; vm[u][3] = t4.w;
            }
            #pragma unroll
            for (int i = 0; i < 4; i++)
                #pragma unroll
                for (int j = 0; j < 4; j++)
                    #pragma unroll
                    for (int u = 0; u < 4; u++)
                        o[i][j] = fmaf(pr[i][u], vm[u][j], o[i][j]);
        }
    }

    #pragma unroll
    for (int i = 0; i < 4; i++) {
        float inv = 1.0f / l_run[i];
        float4 v = make_float4(o[i][0] * inv, o[i][1] * inv,
                               o[i][2] * inv, o[i][3] * inv);
        *(float4*)(go + (size_t)(qBase + ty * 4 + i) * Dd + tx * 4) = v;
    }
}

// ---------------------------------------------------------------------------
// Kernel 3: output projection, 128x128 SGEMM with gather from [B,H,T,D] O.
// ---------------------------------------------------------------------------
__global__ __launch_bounds__(256) void proj_kernel(
    const float* __restrict__ wp, float* __restrict__ out)
{
    __shared__ float As[16][128];
    __shared__ float Bs[16][128];
    const int tid = threadIdx.x;
    const int rowBase = blockIdx.x * 128;
    const int cBase = blockIdx.y * 128;
    const int tx = tid & 15, ty = tid >> 4;

    float acc[8][8];
    #pragma unroll
    for (int i = 0; i < 8; i++)
        #pragma unroll
        for (int j = 0; j < 8; j++) acc[i][j] = 0.f;

    for (int k0 = 0; k0 < Cc; k0 += 16) {
        #pragma unroll
        for (int l = 0; l < 2; l++) {
            int fid = tid + l * 256;
            int m = fid >> 2;
            int kq = (fid & 3) << 2;
            int r = rowBase + m;
            int b = r >> 11, t = r & (Tt - 1);
            int k = k0 + kq;
            const float* src = g_O + ((size_t)(b * Hh + (k >> 6)) * Tt + t) * Dd + (k & 63);
            float4 v = *(const float4*)src;
            As[kq + 0][m] = v.x; As[kq + 1][m] = v.y;
            As[kq + 2][m] = v.z; As[kq + 3][m] = v.w;
        }
        #pragma unroll
        for (int l = 0; l < 2; l++) {
            int fid = tid + l * 256;
            int c = fid >> 2;
            int kq = (fid & 3) << 2;
            float4 v = *(const float4*)(wp + (size_t)(cBase + c) * Cc + k0 + kq);
            Bs[kq + 0][c] = v.x; Bs[kq + 1][c] = v.y;
            Bs[kq + 2][c] = v.z; Bs[kq + 3][c] = v.w;
        }
        __syncthreads();
        #pragma unroll
        for (int kk = 0; kk < 16; kk++) {
            float4 a0 = *(const float4*)&As[kk][ty * 8];
            float4 a1 = *(const float4*)&As[kk][ty * 8 + 4];
            float4 b0 = *(const float4*)&Bs[kk][tx * 8];
            float4 b1 = *(const float4*)&Bs[kk][tx * 8 + 4];
            float a[8] = {a0.x, a0.y, a0.z, a0.w, a1.x, a1.y, a1.z, a1.w};
            float bb[8] = {b0.x, b0.y, b0.z, b0.w, b1.x, b1.y, b1.z, b1.w};
            #pragma unroll
            for (int i = 0; i < 8; i++)
                #pragma unroll
                for (int j = 0; j < 8; j++)
                    acc[i][j] = fmaf(a[i], bb[j], acc[i][j]);
        }
        __syncthreads();
    }

    #pragma unroll
    for (int i = 0; i < 8; i++) {
        int r = rowBase + ty * 8 + i;
        *(float4*)(out + (size_t)r * Cc + cBase + tx * 8) =
            make_float4(acc[i][0], acc[i][1], acc[i][2], acc[i][3]);
        *(float4*)(out + (size_t)r * Cc + cBase + tx * 8 + 4) =
            make_float4(acc[i][4], acc[i][5], acc[i][6], acc[i][7]);
    }
}

// ---------------------------------------------------------------------------
extern "C" void kernel_launch(void* const* d_in, const int* in_sizes, int n_in,
                              void* d_out, int out_size)
{
    (void)in_sizes; (void)n_in; (void)out_size;
    const float* x  = (const float*)d_in[0];
    const float* wq = (const float*)d_in[1];
    const float* wk = (const float*)d_in[2];
    const float* wv = (const float*)d_in[3];
    const float* wp = (const float*)d_in[4];
    float* out = (float*)d_out;

    qkv_kernel<<<dim3(32, 48), 256>>>(x, wq, wk, wv);

    const int SMEM_ATTN = 3 * 64 * 68 * (int)sizeof(float);  // 52224 B
    cudaFuncSetAttribute(attn_kernel,
                         cudaFuncAttributeMaxDynamicSharedMemorySize, SMEM_ATTN);
    attn_kernel<<<dim3(32, 32), 256, SMEM_ATTN>>>();

    proj_kernel<<<dim3(32, 8), 256>>>(wp, out);
}

// round 3
// speedup vs baseline: 2.5450x; 2.5450x over previous
#include <cuda_runtime.h>
#include <cuda_bf16.h>
#include <math.h>
#include <stdint.h>

#define Bb 2
#define Tt 2048
#define Cc 1024
#define Hh 16
#define Dd 64
#define RMS_EPS 1.1920928955078125e-07f

// ---------------- scratch (allocation-free device globals) ----------------
__device__ __nv_bfloat16 g_Xhi[(size_t)4096*1024];
__device__ __nv_bfloat16 g_Xlo[(size_t)4096*1024];
__device__ __nv_bfloat16 g_Whi[(size_t)3072*1024];   // wq|wk|wv stacked rows
__device__ __nv_bfloat16 g_Wlo[(size_t)3072*1024];
__device__ __nv_bfloat16 g_Phi[(size_t)1024*1024];   // w_proj
__device__ __nv_bfloat16 g_Plo[(size_t)1024*1024];
__device__ __nv_bfloat16 g_Qh[(size_t)Bb*Hh*Tt*Dd];
__device__ __nv_bfloat16 g_Ql[(size_t)Bb*Hh*Tt*Dd];
__device__ __nv_bfloat16 g_Kh[(size_t)Bb*Hh*Tt*Dd];
__device__ __nv_bfloat16 g_Kl[(size_t)Bb*Hh*Tt*Dd];
__device__ __nv_bfloat16 g_Vh[(size_t)Bb*Hh*Tt*Dd];
__device__ __nv_bfloat16 g_Vl[(size_t)Bb*Hh*Tt*Dd];
__device__ __nv_bfloat16 g_Ohi[(size_t)4096*1024];   // attention out, [(b,t)][(h,d)]
__device__ __nv_bfloat16 g_Olo[(size_t)4096*1024];

// ---------------- helpers ----------------
__device__ __forceinline__ uint32_t smem_u32(const void* p) {
    uint32_t a;
    asm("{ .reg .u64 t; cvta.to.shared.u64 t, %1; cvt.u32.u64 %0, t; }" : "=r"(a) : "l"(p));
    return a;
}
__device__ __forceinline__ void cp16(uint32_t s, const void* g) {
    asm volatile("cp.async.cg.shared.global [%0], [%1], 16;" :: "r"(s), "l"(g));
}
#define CP_COMMIT() asm volatile("cp.async.commit_group;" ::: "memory")
#define CP_WAIT0()  asm volatile("cp.async.wait_group 0;" ::: "memory")
#define CP_WAIT1()  asm volatile("cp.async.wait_group 1;" ::: "memory")

__device__ __forceinline__ void ldsm4(uint32_t* r, uint32_t a) {
    asm volatile("ldmatrix.sync.aligned.m8n8.x4.shared.b16 {%0,%1,%2,%3}, [%4];"
                 : "=r"(r[0]), "=r"(r[1]), "=r"(r[2]), "=r"(r[3]) : "r"(a));
}
__device__ __forceinline__ void ldsm2(uint32_t* r, uint32_t a) {
    asm volatile("ldmatrix.sync.aligned.m8n8.x2.shared.b16 {%0,%1}, [%2];"
                 : "=r"(r[0]), "=r"(r[1]) : "r"(a));
}
__device__ __forceinline__ void ldsm2t(uint32_t* r, uint32_t a) {
    asm volatile("ldmatrix.sync.aligned.m8n8.x2.trans.shared.b16 {%0,%1}, [%2];"
                 : "=r"(r[0]), "=r"(r[1]) : "r"(a));
}
__device__ __forceinline__ void mma_bf(float* d, const uint32_t* a, const uint32_t* b) {
    asm volatile(
        "mma.sync.aligned.m16n8k16.row.col.f32.bf16.bf16.f32 "
        "{%0,%1,%2,%3}, {%4,%5,%6,%7}, {%8,%9}, {%0,%1,%2,%3};"
        : "+f"(d[0]), "+f"(d[1]), "+f"(d[2]), "+f"(d[3])
        : "r"(a[0]), "r"(a[1]), "r"(a[2]), "r"(a[3]), "r"(b[0]), "r"(b[1]));
}
// split two fp32 into packed bf16x2 hi and lo words (elem a -> low half)
__device__ __forceinline__ void split2(float a, float b, uint32_t& h, uint32_t& l) {
    __nv_bfloat16 ah = __float2bfloat16(a), bh = __float2bfloat16(b);
    float al = a - __bfloat162float(ah);
    float bl = b - __bfloat162float(bh);
    __nv_bfloat162 hv; hv.x = ah; hv.y = bh;
    __nv_bfloat162 lv; lv.x = __float2bfloat16(al); lv.y = __float2bfloat16(bl);
    h = *reinterpret_cast<uint32_t*>(&hv);
    l = *reinterpret_cast<uint32_t*>(&lv);
}

// ---------------- convert: fp32 -> bf16 hi/lo ----------------
__global__ void convert_split(const float* __restrict__ src, int sel, int offElems)
{
    int i = (blockIdx.x * 256 + threadIdx.x) * 4;
    float4 v = *(const float4*)(src + i);
    __nv_bfloat16* hi = (sel == 0) ? g_Xhi : (sel == 1) ? g_Whi : g_Phi;
    __nv_bfloat16* lo = (sel == 0) ? g_Xlo : (sel == 1) ? g_Wlo : g_Plo;
    float f[4] = {v.x, v.y, v.z, v.w};
    __nv_bfloat16 h[4], l[4];
    #pragma unroll
    for (int j = 0; j < 4; j++) {
        h[j] = __float2bfloat16(f[j]);
        l[j] = __float2bfloat16(f[j] - __bfloat162float(h[j]));
    }
    *(uint2*)(hi + offElems + i) = *(uint2*)h;
    *(uint2*)(lo + offElems + i) = *(uint2*)l;
}

// ---------------------------------------------------------------------------
// GEMM: Y[4096 x N] = A[4096 x 1024] * B[N x 1024]^T  via bf16 3-pass split.
// CTA tile 128x128, BK=32, 8 warps (warp tile 64x32).
// mode 0: A=X, B=W(3072 rows); epilogue RMSNorm+RoPE -> g_Q/K/V hi/lo
// mode 1: A=O,  B=P(1024 rows); epilogue -> fp32 out
// ---------------------------------------------------------------------------
#define GS_STAGE 40960                 // 4 arrays * 128 rows * 80B
#define GS_TOTAL (2 * GS_STAGE)

__global__ __launch_bounds__(256) void gemm_mma(float* __restrict__ out, int mode)
{
    extern __shared__ __align__(16) char dyn[];
    __shared__ float invf[32];
    const uint32_t sb = smem_u32(dyn);
    const int tid = threadIdx.x, wid = tid >> 5, lane = tid & 31;
    const int wm = wid >> 2, wn = wid & 3;
    const int rBase = blockIdx.x * 128, nBase = blockIdx.y * 128;

    const __nv_bfloat16 *Ahi, *Alo, *Bhi, *Blo;
    if (mode == 0) { Ahi = g_Xhi; Alo = g_Xlo; Bhi = g_Whi; Blo = g_Wlo; }
    else           { Ahi = g_Ohi; Alo = g_Olo; Bhi = g_Phi; Blo = g_Plo; }

    if (mode == 0 && tid < 32)
        invf[tid] = powf(10000.0f, -((float)(2 * tid)) / 64.0f);

    auto load_chunk = [&](int c, int s) {
        const uint32_t base = sb + s * GS_STAGE;
        const int k0 = c * 32;
        #pragma unroll
        for (int i = 0; i < 2; i++) {
            int f = tid * 2 + i;            // 0..511
            int row = f >> 2, seg = f & 3;  // 4 x 16B per row
            uint32_t so = row * 80 + seg * 16;
            size_t ga = (size_t)(rBase + row) * 1024 + k0 + seg * 8;
            size_t gb = (size_t)(nBase + row) * 1024 + k0 + seg * 8;
            cp16(base + so,          Ahi + ga);
            cp16(base + 10240 + so,  Alo + ga);
            cp16(base + 20480 + so,  Bhi + gb);
            cp16(base + 30720 + so,  Blo + gb);
        }
        CP_COMMIT();
    };

    float C[4][4][4];
    #pragma unroll
    for (int a = 0; a < 4; a++)
        #pragma unroll
        for (int b = 0; b < 4; b++)
            #pragma unroll
            for (int e = 0; e < 4; e++) C[a][b][e] = 0.f;

    load_chunk(0, 0);
    load_chunk(1, 1);

    for (int c = 0; c < 32; c++) {
        CP_WAIT1();
        __syncthreads();
        const uint32_t base = sb + (c & 1) * GS_STAGE;
        #pragma unroll
        for (int ks = 0; ks < 2; ks++) {
            uint32_t Ah[4][4], Al[4][4], Bh[4][2], Bl[4][2];
            const uint32_t acol = ks * 32 + (lane >> 4) * 16;
            #pragma unroll
            for (int mt = 0; mt < 4; mt++) {
                int row = wm * 64 + mt * 16 + (lane & 15);
                ldsm4(Ah[mt], base + row * 80 + acol);
                ldsm4(Al[mt], base + 10240 + row * 80 + acol);
            }
            const uint32_t bcol = ks * 32 + ((lane >> 3) & 1) * 16;
            #pragma unroll
            for (int nt = 0; nt < 4; nt++) {
                int nrow = wn * 32 + nt * 8 + (lane & 7);
                ldsm2(Bh[nt], base + 20480 + nrow * 80 + bcol);
                ldsm2(Bl[nt], base + 30720 + nrow * 80 + bcol);
            }
            #pragma unroll
            for (int mt = 0; mt < 4; mt++)
                #pragma unroll
                for (int nt = 0; nt < 4; nt++) {
                    mma_bf(C[mt][nt], Ah[mt], Bh[nt]);
                    mma_bf(C[mt][nt], Ah[mt], Bl[nt]);
                    mma_bf(C[mt][nt], Al[mt], Bh[nt]);
                }
        }
        __syncthreads();
        if (c + 2 < 32) load_chunk(c + 2, c & 1);
    }

    if (mode == 1) {
        #pragma unroll
        for (int mt = 0; mt < 4; mt++)
            #pragma unroll
            for (int nt = 0; nt < 4; nt++) {
                int r0 = rBase + wm * 64 + mt * 16 + (lane >> 2);
                int cc = nBase + wn * 32 + nt * 8 + 2 * (lane & 3);
                *(float2*)(out + (size_t)r0 * 1024 + cc) =
                    make_float2(C[mt][nt][0], C[mt][nt][1]);
                *(float2*)(out + (size_t)(r0 + 8) * 1024 + cc) =
                    make_float2(C[mt][nt][2], C[mt][nt][3]);
            }
        return;
    }

    // ---- mode 0: stage C tile through smem (reuse pipeline buffers) ----
    float* Cs = (float*)dyn;   // [128][132]
    __syncthreads();
    #pragma unroll
    for (int mt = 0; mt < 4; mt++)
        #pragma unroll
        for (int nt = 0; nt < 4; nt++) {
            int r0 = wm * 64 + mt * 16 + (lane >> 2);
            int cc = wn * 32 + nt * 8 + 2 * (lane & 3);
            *(float2*)&Cs[r0 * 132 + cc] = make_float2(C[mt][nt][0], C[mt][nt][1]);
            *(float2*)&Cs[(r0 + 8) * 132 + cc] = make_float2(C[mt][nt][2], C[mt][nt][3]);
        }
    __syncthreads();

    const int rowL = tid >> 1, headSel = tid & 1;
    const int r = rBase + rowL;
    const int b = r >> 11, t = r & (Tt - 1);
    const int gcol = nBase + headSel * 64;
    const int mat = gcol >> 10;
    const int head = (gcol & 1023) >> 6;

    float v[64];
    #pragma unroll
    for (int j = 0; j < 64; j++) v[j] = Cs[rowL * 132 + headSel * 64 + j];

    float o[64];
    if (mat == 2) {
        #pragma unroll
        for (int j = 0; j < 64; j++) o[j] = v[j];
    } else {
        float ss = 0.f;
        #pragma unroll
        for (int j = 0; j < 64; j++) ss += v[j] * v[j];
        const float scl = rsqrtf(ss * (1.0f / 64.0f) + RMS_EPS);
        const float tf = (float)t;
        #pragma unroll
        for (int i = 0; i < 32; i++) {
            float x1 = v[i] * scl, x2 = v[i + 32] * scl;
            float sn, cn;
            sincosf(tf * invf[i], &sn, &cn);
            o[i] = fmaf(x1, cn, x2 * sn);
            o[i + 32] = fmaf(x2, cn, -x1 * sn);
        }
    }
    __nv_bfloat16 hb[64], lb[64];
    #pragma unroll
    for (int j = 0; j < 64; j++) {
        hb[j] = __float2bfloat16(o[j]);
        lb[j] = __float2bfloat16(o[j] - __bfloat162float(hb[j]));
    }
    __nv_bfloat16* dh = (mat == 0) ? g_Qh : (mat == 1) ? g_Kh : g_Vh;
    __nv_bfloat16* dl = (mat == 0) ? g_Ql : (mat == 1) ? g_Kl : g_Vl;
    size_t doff = ((size_t)(b * Hh + head) * Tt + t) * Dd;
    #pragma unroll
    for (int j = 0; j < 64; j += 8) {
        *(uint4*)(dh + doff + j) = *(uint4*)(hb + j);
        *(uint4*)(dl + doff + j) = *(uint4*)(lb + j);
    }
}

// ---------------------------------------------------------------------------
// Flash attention via mma.sync: 128 q rows per CTA (1 warp = 16 rows),
// kv chunks of 64, 3-pass bf16 split for QK^T and PV.
// smem/stage: Kh,Kl,Vh,Vl each 64 rows x 144B = 9216B -> 36864B; 2 stages.
// ---------------------------------------------------------------------------
#define AS_STAGE 36864
#define AS_TOTAL (2 * AS_STAGE)

__global__ __launch_bounds__(256) void attn_mma()
{
    extern __shared__ __align__(16) char dyn[];
    const uint32_t sb = smem_u32(dyn);
    const int tid = threadIdx.x, wid = tid >> 5, lane = tid & 31;
    const int qt = 15 - (int)blockIdx.x;       // heavy tiles first
    const int bh = blockIdx.y;
    const int qBase = qt * 128;
    const size_t hoff = (size_t)bh * Tt * Dd;

    // ---- stage Q (128 x 64, hi/lo) into stage0, ldmatrix to regs ----
    #pragma unroll
    for (int i = 0; i < 4; i++) {
        int f = tid * 4 + i;              // 0..1023
        int row = f >> 3, seg = f & 7;
        uint32_t so = row * 144 + seg * 16;
        size_t ga = hoff + (size_t)(qBase + row) * 64 + seg * 8;
        cp16(sb + so, g_Qh + ga);
        cp16(sb + 18432 + so, g_Ql + ga);
    }
    CP_COMMIT();
    CP_WAIT0();
    __syncthreads();

    uint32_t Qh[4][4], Ql[4][4];
    {
        int qrow = wid * 16 + (lane & 15);
        #pragma unroll
        for (int ks = 0; ks < 4; ks++) {
            uint32_t col = ks * 32 + (lane >> 4) * 16;
            ldsm4(Qh[ks], sb + qrow * 144 + col);
            ldsm4(Ql[ks], sb + 18432 + qrow * 144 + col);
        }
    }
    __syncthreads();

    auto load_chunk = [&](int kt, int s) {
        const uint32_t base = sb + s * AS_STAGE;
        const int kvb = kt * 64;
        #pragma unroll
        for (int i = 0; i < 2; i++) {
            int f = tid * 2 + i;          // 0..511
            int row = f >> 3, seg = f & 7;
            uint32_t so = row * 144 + seg * 16;
            size_t ga = hoff + (size_t)(kvb + row) * 64 + seg * 8;
            cp16(base + so,          g_Kh + ga);
            cp16(base + 9216 + so,   g_Kl + ga);
            cp16(base + 18432 + so,  g_Vh + ga);
            cp16(base + 27648 + so,  g_Vl + ga);
        }
        CP_COMMIT();
    };

    float O[8][4];
    #pragma unroll
    for (int nt = 0; nt < 8; nt++)
        #pragma unroll
        for (int e = 0; e < 4; e++) O[nt][e] = 0.f;
    float mr[2] = {-1e30f, -1e30f}, lr[2] = {0.f, 0.f};

    const int nChunks = 2 * qt + 2;
    load_chunk(0, 0);
    load_chunk(1, 1);

    const int r0 = qBase + wid * 16 + (lane >> 2);

    for (int ct = 0; ct < nChunks; ct++) {
        if (ct + 1 < nChunks) { CP_WAIT1(); } else { CP_WAIT0(); }
        __syncthreads();
        const uint32_t base = sb + (ct & 1) * AS_STAGE;

        // ---- S = Q K^T ----
        float S[8][4];
        #pragma unroll
        for (int nt = 0; nt < 8; nt++)
            #pragma unroll
            for (int e = 0; e < 4; e++) S[nt][e] = 0.f;

        #pragma unroll
        for (int ks = 0; ks < 4; ks++) {
            const uint32_t bcol = ks * 32 + ((lane >> 3) & 1) * 16;
            #pragma unroll
            for (int nt = 0; nt < 8; nt++) {
                uint32_t Bh[2], Bl[2];
                int nrow = nt * 8 + (lane & 7);
                ldsm2(Bh, base + nrow * 144 + bcol);
                ldsm2(Bl, base + 9216 + nrow * 144 + bcol);
                mma_bf(S[nt], Qh[ks], Bh);
                mma_bf(S[nt], Qh[ks], Bl);
                mma_bf(S[nt], Ql[ks], Bh);
            }
        }

        // ---- scale + causal mask ----
        const int kvBase = ct * 64;
        const bool needMask = (ct >= 2 * qt);
        #pragma unroll
        for (int nt = 0; nt < 8; nt++)
            #pragma unroll
            for (int e = 0; e < 4; e++) {
                S[nt][e] *= 0.125f;
                if (needMask) {
                    int row = r0 + (e >> 1) * 8;
                    int col = kvBase + nt * 8 + 2 * (lane & 3) + (e & 1);
                    if (col > row) S[nt][e] = -1e30f;
                }
            }

        // ---- online softmax (rows r0 [e=0,1], r0+8 [e=2,3]) ----
        #pragma unroll
        for (int half = 0; half < 2; half++) {
            float mx = -1e30f;
            #pragma unroll
            for (int nt = 0; nt < 8; nt++)
                mx = fmaxf(mx, fmaxf(S[nt][2 * half], S[nt][2 * half + 1]));
            mx = fmaxf(mx, __shfl_xor_sync(0xffffffffu, mx, 1));
            mx = fmaxf(mx, __shfl_xor_sync(0xffffffffu, mx, 2));
            float m_new = fmaxf(mr[half], mx);
            float corr = __expf(mr[half] - m_new);
            float rs = 0.f;
            #pragma unroll
            for (int nt = 0; nt < 8; nt++) {
                float p0 = __expf(S[nt][2 * half] - m_new);
                float p1 = __expf(S[nt][2 * half + 1] - m_new);
                S[nt][2 * half] = p0;
                S[nt][2 * half + 1] = p1;
                rs += p0 + p1;
            }
            rs += __shfl_xor_sync(0xffffffffu, rs, 1);
            rs += __shfl_xor_sync(0xffffffffu, rs, 2);
            lr[half] = lr[half] * corr + rs;
            mr[half] = m_new;
            #pragma unroll
            for (int nt = 0; nt < 8; nt++) {
                O[nt][2 * half] *= corr;
                O[nt][2 * half + 1] *= corr;
            }
        }

        // ---- P -> bf16 hi/lo A-fragments (register repack) ----
        uint32_t Ph[4][4], Pl[4][4];
        #pragma unroll
        for (int ks2 = 0; ks2 < 4; ks2++) {
            int t0 = 2 * ks2, t1 = t0 + 1;
            split2(S[t0][0], S[t0][1], Ph[ks2][0], Pl[ks2][0]);
            split2(S[t0][2], S[t0][3], Ph[ks2][1], Pl[ks2][1]);
            split2(S[t1][0], S[t1][1], Ph[ks2][2], Pl[ks2][2]);
            split2(S[t1][2], S[t1][3], Ph[ks2][3], Pl[ks2][3]);
        }

        // ---- O += P V ----
        #pragma unroll
        for (int ks2 = 0; ks2 < 4; ks2++) {
            int kvrow = ks2 * 16 + ((lane >> 3) & 1) * 8 + (lane & 7);
            #pragma unroll
            for (int nt = 0; nt < 8; nt++) {
                uint32_t Vh[2], Vl[2];
                ldsm2t(Vh, base + 18432 + kvrow * 144 + nt * 16);
                ldsm2t(Vl, base + 27648 + kvrow * 144 + nt * 16);
                mma_bf(O[nt], Ph[ks2], Vh);
                mma_bf(O[nt], Ph[ks2], Vl);
                mma_bf(O[nt], Pl[ks2], Vh);
            }
        }

        __syncthreads();
        if (ct + 2 < nChunks) load_chunk(ct + 2, ct & 1);
    }

    // ---- epilogue: O /= l, write bf16 hi/lo to g_Ohi/g_Olo ----
    const int b = bh >> 4, head = bh & 15;
    #pragma unroll
    for (int half = 0; half < 2; half++) {
        float inv = 1.0f / lr[half];
        int t = qBase + wid * 16 + (lane >> 2) + 8 * half;
        size_t rbase = ((size_t)(b * Tt) + t) * 1024 + head * 64;
        #pragma unroll
        for (int nt = 0; nt < 8; nt++) {
            uint32_t h, l;
            split2(O[nt][2 * half] * inv, O[nt][2 * half + 1] * inv, h, l);
            size_t off = rbase + nt * 8 + 2 * (lane & 3);
            *(uint32_t*)(g_Ohi + off) = h;
            *(uint32_t*)(g_Olo + off) = l;
        }
    }
}

// ---------------------------------------------------------------------------
extern "C" void kernel_launch(void* const* d_in, const int* in_sizes, int n_in,
                              void* d_out, int out_size)
{
    (void)in_sizes; (void)n_in; (void)out_size;
    const float* x  = (const float*)d_in[0];
    const float* wq = (const float*)d_in[1];
    const float* wk = (const float*)d_in[2];
    const float* wv = (const float*)d_in[3];
    const float* wp = (const float*)d_in[4];
    float* out = (float*)d_out;

    convert_split<<<4096, 256>>>(x,  0, 0);
    convert_split<<<1024, 256>>>(wq, 1, 0);
    convert_split<<<1024, 256>>>(wk, 1, 1048576);
    convert_split<<<1024, 256>>>(wv, 1, 2097152);
    convert_split<<<1024, 256>>>(wp, 2, 0);

    cudaFuncSetAttribute(gemm_mma, cudaFuncAttributeMaxDynamicSharedMemorySize, GS_TOTAL);
    cudaFuncSetAttribute(attn_mma, cudaFuncAttributeMaxDynamicSharedMemorySize, AS_TOTAL);

    gemm_mma<<<dim3(32, 24), 256, GS_TOTAL>>>(nullptr, 0);   // QKV + norm + rope
    attn_mma<<<dim3(16, 32), 256, AS_TOTAL>>>();             // flash attention
    gemm_mma<<<dim3(32, 8), 256, GS_TOTAL>>>(out, 1);        // output projection
}

// round 6
// speedup vs baseline: 3.9796x; 1.5637x over previous
#include <cuda_runtime.h>
#include <cuda_fp16.h>
#include <math.h>
#include <stdint.h>

#define Bb 2
#define Tt 2048
#define Cc 1024
#define Hh 16
#define Dd 64
#define RMS_EPS 1.1920928955078125e-07f

// ---------------- scratch (allocation-free device globals) ----------------
__device__ __half g_Xhi[(size_t)4096*1024];
__device__ __half g_Xlo[(size_t)4096*1024];
__device__ __half g_Wh [(size_t)3072*1024];   // wq|wk|wv stacked rows, fp16
__device__ __half g_Ph [(size_t)1024*1024];   // w_proj fp16
__device__ __half g_Qh [(size_t)Bb*Hh*Tt*Dd];
__device__ __half g_Ql [(size_t)Bb*Hh*Tt*Dd];
__device__ __half g_Kh [(size_t)Bb*Hh*Tt*Dd];
__device__ __half g_Vh [(size_t)Bb*Hh*Tt*Dd];
__device__ __half g_Ohi[(size_t)4096*1024];   // attention out, [(b,t)][(h,d)]
__device__ __half g_Olo[(size_t)4096*1024];

// ---------------- helpers ----------------
__device__ __forceinline__ uint32_t smem_u32(const void* p) {
    uint32_t a;
    asm("{ .reg .u64 t; cvta.to.shared.u64 t, %1; cvt.u32.u64 %0, t; }" : "=r"(a) : "l"(p));
    return a;
}
__device__ __forceinline__ void cp16(uint32_t s, const void* g) {
    asm volatile("cp.async.cg.shared.global [%0], [%1], 16;" :: "r"(s), "l"(g));
}
#define CP_COMMIT() asm volatile("cp.async.commit_group;" ::: "memory")
#define CP_WAIT0()  asm volatile("cp.async.wait_group 0;" ::: "memory")
#define CP_WAIT1()  asm volatile("cp.async.wait_group 1;" ::: "memory")

__device__ __forceinline__ void ldsm4(uint32_t* r, uint32_t a) {
    asm volatile("ldmatrix.sync.aligned.m8n8.x4.shared.b16 {%0,%1,%2,%3}, [%4];"
                 : "=r"(r[0]), "=r"(r[1]), "=r"(r[2]), "=r"(r[3]) : "r"(a));
}
__device__ __forceinline__ void ldsm2(uint32_t* r, uint32_t a) {
    asm volatile("ldmatrix.sync.aligned.m8n8.x2.shared.b16 {%0,%1}, [%2];"
                 : "=r"(r[0]), "=r"(r[1]) : "r"(a));
}
__device__ __forceinline__ void ldsm2t(uint32_t* r, uint32_t a) {
    asm volatile("ldmatrix.sync.aligned.m8n8.x2.trans.shared.b16 {%0,%1}, [%2];"
                 : "=r"(r[0]), "=r"(r[1]) : "r"(a));
}
__device__ __forceinline__ void mma_fp(float* d, const uint32_t* a, const uint32_t* b) {
    asm volatile(
        "mma.sync.aligned.m16n8k16.row.col.f32.f16.f16.f32 "
        "{%0,%1,%2,%3}, {%4,%5,%6,%7}, {%8,%9}, {%0,%1,%2,%3};"
        : "+f"(d[0]), "+f"(d[1]), "+f"(d[2]), "+f"(d[3])
        : "r"(a[0]), "r"(a[1]), "r"(a[2]), "r"(a[3]), "r"(b[0]), "r"(b[1]));
}
// split two fp32 into packed fp16x2 hi and lo words (elem a -> low half)
__device__ __forceinline__ void split2(float a, float b, uint32_t& h, uint32_t& l) {
    __half ah = __float2half_rn(a), bh = __float2half_rn(b);
    float al = a - __half2float(ah);
    float bl = b - __half2float(bh);
    __half hv[2] = {ah, bh};
    __half lv[2] = {__float2half_rn(al), __float2half_rn(bl)};
    h = *reinterpret_cast<uint32_t*>(hv);
    l = *reinterpret_cast<uint32_t*>(lv);
}

// ---------------- converts ----------------
__global__ void convert_x(const float* __restrict__ src)
{
    int i = (blockIdx.x * 256 + threadIdx.x) * 4;
    float4 v = *(const float4*)(src + i);
    float f[4] = {v.x, v.y, v.z, v.w};
    __half h[4], l[4];
    #pragma unroll
    for (int j = 0; j < 4; j++) {
        h[j] = __float2half_rn(f[j]);
        l[j] = __float2half_rn(f[j] - __half2float(h[j]));
    }
    *(uint2*)(g_Xhi + i) = *(uint2*)h;
    *(uint2*)(g_Xlo + i) = *(uint2*)l;
}
__global__ void convert_w(const float* __restrict__ src, int sel, int offElems)
{
    int i = (blockIdx.x * 256 + threadIdx.x) * 4;
    float4 v = *(const float4*)(src + i);
    __half h[4] = {__float2half_rn(v.x), __float2half_rn(v.y),
                   __float2half_rn(v.z), __float2half_rn(v.w)};
    __half* dst = (sel == 0) ? g_Wh : g_Ph;
    *(uint2*)(dst + offElems + i) = *(uint2*)h;
}

// ---------------------------------------------------------------------------
// GEMM: Y[4096 x N] = A[4096 x 1024] * B[N x 1024]^T, fp16 2-pass (A split).
// CTA tile 128x128, BK=32, 8 warps (warp tile 64x32).
// mode 0: A=Xhi/Xlo, B=Wh; epilogue RMSNorm+RoPE -> Q(hi/lo), K, V
// mode 1: A=Ohi/Olo, B=Ph; epilogue -> fp32 out
// Dynamic smem = max(2*GS_STAGE, 128*132*4 C-tile) = 67584 B.
// ---------------------------------------------------------------------------
#define GS_STAGE 30720                 // 3 arrays * 128 rows * 80B
#define GS_DYN   67584                 // C-tile 128 x 132 fp32 dominates

__global__ __launch_bounds__(256) void gemm_mma(float* __restrict__ out, int mode)
{
    extern __shared__ __align__(16) char dyn[];
    __shared__ float invf[32];
    const uint32_t sb = smem_u32(dyn);
    const int tid = threadIdx.x, wid = tid >> 5, lane = tid & 31;
    const int wm = wid >> 2, wn = wid & 3;
    const int rBase = blockIdx.x * 128, nBase = blockIdx.y * 128;

    const __half *Ahi, *Alo, *Bh;
    if (mode == 0) { Ahi = g_Xhi; Alo = g_Xlo; Bh = g_Wh; }
    else           { Ahi = g_Ohi; Alo = g_Olo; Bh = g_Ph; }

    if (mode == 0 && tid < 32)
        invf[tid] = exp2f((float)(-2 * tid) * (0.015625f * 13.287712379549449f));
        // invf[i] = 10000^(-2i/64)

    auto load_chunk = [&](int c, int s) {
        const uint32_t base = sb + s * GS_STAGE;
        const int k0 = c * 32;
        #pragma unroll
        for (int i = 0; i < 2; i++) {
            int f = tid * 2 + i;            // 0..511
            int row = f >> 2, seg = f & 3;  // 4 x 16B per row
            uint32_t so = row * 80 + seg * 16;
            size_t ga = (size_t)(rBase + row) * 1024 + k0 + seg * 8;
            size_t gb = (size_t)(nBase + row) * 1024 + k0 + seg * 8;
            cp16(base + so,          Ahi + ga);
            cp16(base + 10240 + so,  Alo + ga);
            cp16(base + 20480 + so,  Bh  + gb);
        }
        CP_COMMIT();
    };

    float C[4][4][4];
    #pragma unroll
    for (int a = 0; a < 4; a++)
        #pragma unroll
        for (int b = 0; b < 4; b++)
            #pragma unroll
            for (int e = 0; e < 4; e++) C[a][b][e] = 0.f;

    load_chunk(0, 0);
    load_chunk(1, 1);

    for (int c = 0; c < 32; c++) {
        CP_WAIT1();
        __syncthreads();
        const uint32_t base = sb + (c & 1) * GS_STAGE;
        #pragma unroll
        for (int ks = 0; ks < 2; ks++) {
            uint32_t Ah[4][4], Al[4][4], Bf[4][2];
            const uint32_t acol = ks * 32 + (lane >> 4) * 16;
            #pragma unroll
            for (int mt = 0; mt < 4; mt++) {
                int row = wm * 64 + mt * 16 + (lane & 15);
                ldsm4(Ah[mt], base + row * 80 + acol);
                ldsm4(Al[mt], base + 10240 + row * 80 + acol);
            }
            const uint32_t bcol = ks * 32 + ((lane >> 3) & 1) * 16;
            #pragma unroll
            for (int nt = 0; nt < 4; nt++) {
                int nrow = wn * 32 + nt * 8 + (lane & 7);
                ldsm2(Bf[nt], base + 20480 + nrow * 80 + bcol);
            }
            #pragma unroll
            for (int mt = 0; mt < 4; mt++)
                #pragma unroll
                for (int nt = 0; nt < 4; nt++) {
                    mma_fp(C[mt][nt], Ah[mt], Bf[nt]);
                    mma_fp(C[mt][nt], Al[mt], Bf[nt]);
                }
        }
        __syncthreads();
        if (c + 2 < 32) load_chunk(c + 2, c & 1);
    }

    if (mode == 1) {
        #pragma unroll
        for (int mt = 0; mt < 4; mt++)
            #pragma unroll
            for (int nt = 0; nt < 4; nt++) {
                int r0 = rBase + wm * 64 + mt * 16 + (lane >> 2);
                int cc = nBase + wn * 32 + nt * 8 + 2 * (lane & 3);
                *(float2*)(out + (size_t)r0 * 1024 + cc) =
                    make_float2(C[mt][nt][0], C[mt][nt][1]);
                *(float2*)(out + (size_t)(r0 + 8) * 1024 + cc) =
                    make_float2(C[mt][nt][2], C[mt][nt][3]);
            }
        return;
    }

    // ---- mode 0: stage C tile through smem; stride 132 >= 128 cols ----
    float* Cs = (float*)dyn;   // [128][132] fp32 = 67584 B = GS_DYN
    __syncthreads();
    #pragma unroll
    for (int mt = 0; mt < 4; mt++)
        #pragma unroll
        for (int nt = 0; nt < 4; nt++) {
            int r0 = wm * 64 + mt * 16 + (lane >> 2);
            int cc = wn * 32 + nt * 8 + 2 * (lane & 3);
            *(float2*)&Cs[r0 * 132 + cc] = make_float2(C[mt][nt][0], C[mt][nt][1]);
            *(float2*)&Cs[(r0 + 8) * 132 + cc] = make_float2(C[mt][nt][2], C[mt][nt][3]);
        }
    __syncthreads();

    const int rowL = tid >> 1, headSel = tid & 1;
    const int r = rBase + rowL;
    const int b = r >> 11, t = r & (Tt - 1);
    const int gcol = nBase + headSel * 64;
    const int mat = gcol >> 10;
    const int head = (gcol & 1023) >> 6;

    float v[64];
    #pragma unroll
    for (int j = 0; j < 64; j++) v[j] = Cs[rowL * 132 + headSel * 64 + j];

    float o[64];
    if (mat == 2) {
        #pragma unroll
        for (int j = 0; j < 64; j++) o[j] = v[j];
    } else {
        float ss = 0.f;
        #pragma unroll
        for (int j = 0; j < 64; j++) ss += v[j] * v[j];
        const float scl = rsqrtf(ss * (1.0f / 64.0f) + RMS_EPS);
        const float tf = (float)t;
        #pragma unroll
        for (int i = 0; i < 32; i++) {
            float x1 = v[i] * scl, x2 = v[i + 32] * scl;
            float sn, cn;
            sincosf(tf * invf[i], &sn, &cn);
            o[i] = fmaf(x1, cn, x2 * sn);
            o[i + 32] = fmaf(x2, cn, -x1 * sn);
        }
    }
    size_t doff = ((size_t)(b * Hh + head) * Tt + t) * Dd;
    if (mat == 0) {
        __half hb[64], lb[64];
        #pragma unroll
        for (int j = 0; j < 64; j++) {
            hb[j] = __float2half_rn(o[j]);
            lb[j] = __float2half_rn(o[j] - __half2float(hb[j]));
        }
        #pragma unroll
        for (int j = 0; j < 64; j += 8) {
            *(uint4*)(g_Qh + doff + j) = *(uint4*)(hb + j);
            *(uint4*)(g_Ql + doff + j) = *(uint4*)(lb + j);
        }
    } else {
        __half hb[64];
        #pragma unroll
        for (int j = 0; j < 64; j++) hb[j] = __float2half_rn(o[j]);
        __half* dh = (mat == 1) ? g_Kh : g_Vh;
        #pragma unroll
        for (int j = 0; j < 64; j += 8)
            *(uint4*)(dh + doff + j) = *(uint4*)(hb + j);
    }
}

// ---------------------------------------------------------------------------
// Flash attention via fp16 mma: 128 q rows/CTA (1 warp = 16 rows),
// kv chunks of 64, 2-pass split (Q hi/lo, P hi/lo; K, V single fp16).
// smem/stage: Kh, Vh each 64 rows x 144B = 9216B -> 18432B; 2 stages.
// ---------------------------------------------------------------------------
#define AS_STAGE 18432
#define AS_TOTAL (2 * AS_STAGE)

__global__ __launch_bounds__(256) void attn_mma()
{
    extern __shared__ __align__(16) char dyn[];
    const uint32_t sb = smem_u32(dyn);
    const int tid = threadIdx.x, wid = tid >> 5, lane = tid & 31;
    const int qt = 15 - (int)blockIdx.x;       // heavy tiles first
    const int bh = blockIdx.y;
    const int qBase = qt * 128;
    const size_t hoff = (size_t)bh * Tt * Dd;

    // ---- stage Q (128 x 64, hi/lo) across both stage buffers ----
    #pragma unroll
    for (int i = 0; i < 4; i++) {
        int f = tid * 4 + i;              // 0..1023
        int row = f >> 3, seg = f & 7;
        uint32_t so = row * 144 + seg * 16;
        size_t ga = hoff + (size_t)(qBase + row) * 64 + seg * 8;
        cp16(sb + so, g_Qh + ga);
        cp16(sb + 18432 + so, g_Ql + ga);
    }
    CP_COMMIT();
    CP_WAIT0();
    __syncthreads();

    uint32_t Qh[4][4], Ql[4][4];
    {
        int qrow = wid * 16 + (lane & 15);
        #pragma unroll
        for (int ks = 0; ks < 4; ks++) {
            uint32_t col = ks * 32 + (lane >> 4) * 16;
            ldsm4(Qh[ks], sb + qrow * 144 + col);
            ldsm4(Ql[ks], sb + 18432 + qrow * 144 + col);
        }
    }
    __syncthreads();

    auto load_chunk = [&](int kt, int s) {
        const uint32_t base = sb + s * AS_STAGE;
        const int kvb = kt * 64;
        #pragma unroll
        for (int i = 0; i < 2; i++) {
            int f = tid * 2 + i;          // 0..511
            int row = f >> 3, seg = f & 7;
            uint32_t so = row * 144 + seg * 16;
            size_t ga = hoff + (size_t)(kvb + row) * 64 + seg * 8;
            cp16(base + so,          g_Kh + ga);
            cp16(base + 9216 + so,   g_Vh + ga);
        }
        CP_COMMIT();
    };

    float O[8][4];
    #pragma unroll
    for (int nt = 0; nt < 8; nt++)
        #pragma unroll
        for (int e = 0; e < 4; e++) O[nt][e] = 0.f;
    float mr[2] = {-1e30f, -1e30f}, lr[2] = {0.f, 0.f};

    const int nChunks = 2 * qt + 2;
    load_chunk(0, 0);
    load_chunk(1, 1);

    const int r0 = qBase + wid * 16 + (lane >> 2);

    for (int ct = 0; ct < nChunks; ct++) {
        if (ct + 1 < nChunks) { CP_WAIT1(); } else { CP_WAIT0(); }
        __syncthreads();
        const uint32_t base = sb + (ct & 1) * AS_STAGE;

        // ---- S = Q K^T ----
        float S[8][4];
        #pragma unroll
        for (int nt = 0; nt < 8; nt++)
            #pragma unroll
            for (int e = 0; e < 4; e++) S[nt][e] = 0.f;

        #pragma unroll
        for (int ks = 0; ks < 4; ks++) {
            const uint32_t bcol = ks * 32 + ((lane >> 3) & 1) * 16;
            #pragma unroll
            for (int nt = 0; nt < 8; nt++) {
                uint32_t Bf[2];
                int nrow = nt * 8 + (lane & 7);
                ldsm2(Bf, base + nrow * 144 + bcol);
                mma_fp(S[nt], Qh[ks], Bf);
                mma_fp(S[nt], Ql[ks], Bf);
            }
        }

        // ---- scale + causal mask ----
        const int kvBase = ct * 64;
        const bool needMask = (ct >= 2 * qt);
        #pragma unroll
        for (int nt = 0; nt < 8; nt++)
            #pragma unroll
            for (int e = 0; e < 4; e++) {
                S[nt][e] *= 0.125f;
                if (needMask) {
                    int row = r0 + (e >> 1) * 8;
                    int col = kvBase + nt * 8 + 2 * (lane & 3) + (e & 1);
                    if (col > row) S[nt][e] = -1e30f;
                }
            }

        // ---- online softmax ----
        #pragma unroll
        for (int half = 0; half < 2; half++) {
            float mx = -1e30f;
            #pragma unroll
            for (int nt = 0; nt < 8; nt++)
                mx = fmaxf(mx, fmaxf(S[nt][2 * half], S[nt][2 * half + 1]));
            mx = fmaxf(mx, __shfl_xor_sync(0xffffffffu, mx, 1));
            mx = fmaxf(mx, __shfl_xor_sync(0xffffffffu, mx, 2));
            float m_new = fmaxf(mr[half], mx);
            float corr = __expf(mr[half] - m_new);
            float rs = 0.f;
            #pragma unroll
            for (int nt = 0; nt < 8; nt++) {
                float p0 = __expf(S[nt][2 * half] - m_new);
                float p1 = __expf(S[nt][2 * half + 1] - m_new);
                S[nt][2 * half] = p0;
                S[nt][2 * half + 1] = p1;
                rs += p0 + p1;
            }
            rs += __shfl_xor_sync(0xffffffffu, rs, 1);
            rs += __shfl_xor_sync(0xffffffffu, rs, 2);
            lr[half] = lr[half] * corr + rs;
            mr[half] = m_new;
            #pragma unroll
            for (int nt = 0; nt < 8; nt++) {
                O[nt][2 * half] *= corr;
                O[nt][2 * half + 1] *= corr;
            }
        }

        // ---- P -> fp16 hi/lo A-fragments (register repack) ----
        uint32_t Ph[4][4], Pl[4][4];
        #pragma unroll
        for (int ks2 = 0; ks2 < 4; ks2++) {
            int t0 = 2 * ks2, t1 = t0 + 1;
            split2(S[t0][0], S[t0][1], Ph[ks2][0], Pl[ks2][0]);
            split2(S[t0][2], S[t0][3], Ph[ks2][1], Pl[ks2][1]);
            split2(S[t1][0], S[t1][1], Ph[ks2][2], Pl[ks2][2]);
            split2(S[t1][2], S[t1][3], Ph[ks2][3], Pl[ks2][3]);
        }

        // ---- O += P V ----
        #pragma unroll
        for (int ks2 = 0; ks2 < 4; ks2++) {
            int kvrow = ks2 * 16 + ((lane >> 3) & 1) * 8 + (lane & 7);
            #pragma unroll
            for (int nt = 0; nt < 8; nt++) {
                uint32_t Vf[2];
                ldsm2t(Vf, base + 9216 + kvrow * 144 + nt * 16);
                mma_fp(O[nt], Ph[ks2], Vf);
                mma_fp(O[nt], Pl[ks2], Vf);
            }
        }

        __syncthreads();
        if (ct + 2 < nChunks) load_chunk(ct + 2, ct & 1);
    }

    // ---- epilogue: O /= l, write fp16 hi/lo to g_Ohi/g_Olo ----
    const int b = bh >> 4, head = bh & 15;
    #pragma unroll
    for (int half = 0; half < 2; half++) {
        float inv = 1.0f / lr[half];
        int t = qBase + wid * 16 + (lane >> 2) + 8 * half;
        size_t rbase = ((size_t)(b * Tt) + t) * 1024 + head * 64;
        #pragma unroll
        for (int nt = 0; nt < 8; nt++) {
            uint32_t h, l;
            split2(O[nt][2 * half] * inv, O[nt][2 * half + 1] * inv, h, l);
            size_t off = rbase + nt * 8 + 2 * (lane & 3);
            *(uint32_t*)(g_Ohi + off) = h;
            *(uint32_t*)(g_Olo + off) = l;
        }
    }
}

// ---------------------------------------------------------------------------
extern "C" void kernel_launch(void* const* d_in, const int* in_sizes, int n_in,
                              void* d_out, int out_size)
{
    (void)in_sizes; (void)n_in; (void)out_size;
    const float* x  = (const float*)d_in[0];
    const float* wq = (const float*)d_in[1];
    const float* wk = (const float*)d_in[2];
    const float* wv = (const float*)d_in[3];
    const float* wp = (const float*)d_in[4];
    float* out = (float*)d_out;

    convert_x<<<4096, 256>>>(x);
    convert_w<<<1024, 256>>>(wq, 0, 0);
    convert_w<<<1024, 256>>>(wk, 0, 1048576);
    convert_w<<<1024, 256>>>(wv, 0, 2097152);
    convert_w<<<1024, 256>>>(wp, 1, 0);

    cudaFuncSetAttribute(gemm_mma, cudaFuncAttributeMaxDynamicSharedMemorySize, GS_DYN);
    cudaFuncSetAttribute(attn_mma, cudaFuncAttributeMaxDynamicSharedMemorySize, AS_TOTAL);

    gemm_mma<<<dim3(32, 24), 256, GS_DYN>>>(nullptr, 0);     // QKV + norm + rope
    attn_mma<<<dim3(16, 32), 256, AS_TOTAL>>>();             // flash attention
    gemm_mma<<<dim3(32, 8), 256, GS_DYN>>>(out, 1);          // output projection
}